// round 5
// baseline (speedup 1.0000x reference)
#include <cuda_runtime.h>

#define B_      8
#define T_      2048
#define DMODEL  512
#define NHEADS  8
#define HDIM    64
#define BT_     (B_*T_)

// Scratch (device globals) — EXACTLY the R2 footprint (128 MiB): proven safe.
__device__ float g_q[B_*NHEADS*T_*HDIM];   // tf32 bits after rope
__device__ float g_k[B_*NHEADS*T_*HDIM];   // tf32 bits after rope
__device__ float g_v[B_*NHEADS*T_*HDIM];   // tf32 bits (qkv epilogue)
__device__ float g_y[BT_*DMODEL];          // tf32 bits (flash epilogue)

// ---------------------------------------------------------------------------
// helpers
// ---------------------------------------------------------------------------
__device__ __forceinline__ unsigned f2tf(float x) {
    unsigned u;
    asm("cvt.rna.tf32.f32 %0, %1;" : "=r"(u) : "f"(x));
    return u;
}
__device__ __forceinline__ float f2tf_f(float x) { return __uint_as_float(f2tf(x)); }
__device__ __forceinline__ float4 f2tf_4(float4 v) {
    return make_float4(f2tf_f(v.x), f2tf_f(v.y), f2tf_f(v.z), f2tf_f(v.w));
}

__device__ __forceinline__ void mma_tf32(float c[4], const unsigned a[4], const unsigned b[2]) {
    asm volatile(
        "mma.sync.aligned.m16n8k8.row.col.f32.tf32.tf32.f32 "
        "{%0,%1,%2,%3},{%4,%5,%6,%7},{%8,%9},{%0,%1,%2,%3};"
        : "+f"(c[0]), "+f"(c[1]), "+f"(c[2]), "+f"(c[3])
        : "r"(a[0]), "r"(a[1]), "r"(a[2]), "r"(a[3]), "r"(b[0]), "r"(b[1]));
}

__device__ __forceinline__ void cp16(void* smem, const void* g) {
    unsigned s = (unsigned)__cvta_generic_to_shared(smem);
    asm volatile("cp.async.cg.shared.global [%0], [%1], 16;" :: "r"(s), "l"(g));
}
__device__ __forceinline__ void cp_commit() { asm volatile("cp.async.commit_group;"); }

// ---------------------------------------------------------------------------
// tf32 GEMM: C = A @ W + bias.  M=16384, K=512.
// 128x128 tile, 256 threads (8 warps 2x4), warp tile 64x32, K-STEP 32.
// cp.async double-buffered; tf32 conversion ONCE per CTA-tile, in-smem
// (each thread converts exactly the float4s it cp.async'd). mma loop: no cvt.
// SCATTER: epilogue scatters qkv (V rounded to tf32); else writes Out fp32.
// ---------------------------------------------------------------------------
#define AS_S 36
#define BS_S 136
#define GEMM_SMEM ((2*128*AS_S + 2*32*BS_S)*4)   // 71680 B

template<int N, bool SCATTER, bool CVT_A, bool CVT_B>
__global__ __launch_bounds__(256, 2) void gemm_tf32_kernel(
    const float* __restrict__ A, const float* __restrict__ W,
    const float* __restrict__ bias, float* __restrict__ Out)
{
    const int K = DMODEL;
    extern __shared__ float smg[];
    float* Asm = smg;                     // [2][128][AS_S]
    float* Bsm = smg + 2*128*AS_S;        // [2][32][BS_S]

    int tid  = threadIdx.x;
    int lane = tid & 31, warp = tid >> 5;
    int q = lane & 3, r = lane >> 2;
    int wr = warp >> 2, wc = warp & 3;
    int r0 = blockIdx.y << 7, c0 = blockIdx.x << 7;

    const float* Aptr = SCATTER ? A : g_y;

    // loader mapping (k-step 32): A 128x32, B 32x128, 4 float4 each per thread
    int arow = tid >> 1, akb = (tid & 1) << 4;   // A row, k-base (0|16)
    int brow = tid >> 3, bcb = (tid & 7) << 4;   // B k-row, n-base (0..112)

    float acc[4][4][4];
    #pragma unroll
    for (int mi = 0; mi < 4; mi++)
        #pragma unroll
        for (int ni = 0; ni < 4; ni++)
            #pragma unroll
            for (int e = 0; e < 4; e++) acc[mi][ni][e] = 0.f;

    // ---- prefetch tile 0
    #pragma unroll
    for (int j = 0; j < 4; j++) {
        cp16(&Asm[(0*128 + arow)*AS_S + akb + j*4], &Aptr[(size_t)(r0+arow)*K + akb + j*4]);
        cp16(&Bsm[(0*32  + brow)*BS_S + bcb + j*4], &W[(size_t)brow*N + c0 + bcb + j*4]);
    }
    cp_commit();

    int buf = 0;
    for (int it = 0; it < 16; it++) {
        asm volatile("cp.async.wait_group 0;");
        __syncthreads();                       // tile 'buf' arrived for everyone

        if (it + 1 < 16) {                     // async prefetch next tile
            int k0 = (it + 1) << 5;
            int nb = buf ^ 1;
            #pragma unroll
            for (int j = 0; j < 4; j++) {
                cp16(&Asm[(nb*128 + arow)*AS_S + akb + j*4],
                     &Aptr[(size_t)(r0+arow)*K + k0 + akb + j*4]);
                cp16(&Bsm[(nb*32  + brow)*BS_S + bcb + j*4],
                     &W[(size_t)(k0+brow)*N + c0 + bcb + j*4]);
            }
            cp_commit();
        }

        // in-smem tf32 conversion of tile 'buf' (own addresses only)
        if (CVT_A) {
            #pragma unroll
            for (int j = 0; j < 4; j++) {
                float4* p = (float4*)&Asm[(buf*128 + arow)*AS_S + akb + j*4];
                *p = f2tf_4(*p);
            }
        }
        if (CVT_B) {
            #pragma unroll
            for (int j = 0; j < 4; j++) {
                float4* p = (float4*)&Bsm[(buf*32 + brow)*BS_S + bcb + j*4];
                *p = f2tf_4(*p);
            }
        }
        if (CVT_A || CVT_B) __syncthreads();   // converted tile visible

        const float* Ab = &Asm[buf*128*AS_S];
        const float* Bb = &Bsm[buf*32*BS_S];
        #pragma unroll
        for (int ks = 0; ks < 4; ks++) {
            unsigned a[4][4], b[4][2];
            #pragma unroll
            for (int mi = 0; mi < 4; mi++) {
                int mb = wr*64 + mi*16;
                a[mi][0] = __float_as_uint(Ab[(mb + r    )*AS_S + ks*8 + q    ]);
                a[mi][1] = __float_as_uint(Ab[(mb + r + 8)*AS_S + ks*8 + q    ]);
                a[mi][2] = __float_as_uint(Ab[(mb + r    )*AS_S + ks*8 + q + 4]);
                a[mi][3] = __float_as_uint(Ab[(mb + r + 8)*AS_S + ks*8 + q + 4]);
            }
            #pragma unroll
            for (int ni = 0; ni < 4; ni++) {
                int nb2 = wc*32 + ni*8;
                b[ni][0] = __float_as_uint(Bb[(ks*8 + q    )*BS_S + nb2 + r]);
                b[ni][1] = __float_as_uint(Bb[(ks*8 + q + 4)*BS_S + nb2 + r]);
            }
            #pragma unroll
            for (int mi = 0; mi < 4; mi++)
                #pragma unroll
                for (int ni = 0; ni < 4; ni++)
                    mma_tf32(acc[mi][ni], a[mi], b[ni]);
        }
        __syncthreads();                       // done reading buf before next overwrite
        buf ^= 1;
    }

    // ---- epilogue
    #pragma unroll
    for (int mi = 0; mi < 4; mi++) {
        #pragma unroll
        for (int half = 0; half < 2; half++) {
            int row = r0 + wr*64 + mi*16 + r + half*8;
            #pragma unroll
            for (int ni = 0; ni < 4; ni++) {
                int col = c0 + wc*32 + ni*8 + 2*q;
                float v0 = acc[mi][ni][half*2+0] + bias[col];
                float v1 = acc[mi][ni][half*2+1] + bias[col+1];
                if (SCATTER) {
                    int b_ = row >> 11, t = row & (T_-1);
                    int proj = col >> 9;
                    int dm = col & 511;
                    int h = dm >> 6, d = dm & 63;
                    if (proj == 2) { v0 = f2tf_f(v0); v1 = f2tf_f(v1); }  // V pre-rounded
                    float* dst = (proj == 0) ? g_q : (proj == 1) ? g_k : g_v;
                    *(float2*)&dst[(((size_t)(b_<<3) + h)*T_ + t)*HDIM + d] = make_float2(v0, v1);
                } else {
                    *(float2*)&Out[(size_t)row*N + col] = make_float2(v0, v1);
                }
            }
        }
    }
}

// ---------------------------------------------------------------------------
// RoPE on q (scaled by 1/sqrt(D)) and k, in place; writes tf32 bits
// ---------------------------------------------------------------------------
__global__ void rope_kernel()
{
    int idx = blockIdx.x*blockDim.x + threadIdx.x;   // B*H*T*32
    int i  = idx & 31;
    int t  = (idx >> 5) & (T_-1);
    int bh = idx >> 16;
    float invf = exp2f(-(float)i * 0.4152410118609203f);
    float ang  = (float)t * invf;
    float sn, cs;
    sincosf(ang, &sn, &cs);
    int base = (bh*T_ + t)*HDIM + i;
    float q1 = g_q[base], q2 = g_q[base+32];
    g_q[base]    = f2tf_f((q1*cs - q2*sn) * 0.125f);
    g_q[base+32] = f2tf_f((q2*cs + q1*sn) * 0.125f);
    float k1 = g_k[base], k2 = g_k[base+32];
    g_k[base]    = f2tf_f(k1*cs - k2*sn);
    g_k[base+32] = f2tf_f(k2*cs + k1*sn);
}

// ---------------------------------------------------------------------------
// Causal flash attention, tf32 mma. 64 q-rows x 64 keys per tile.
// 4 warps; warp w owns q-rows [w*16, w*16+16).
// K/V pre-rounded tf32 bits in gmem -> cp.async double-buffered natural tiles.
// ---------------------------------------------------------------------------
#define KN_S 68
#define VN_S 72
#define QP_S 76
#define FLASH_SMEM ((2*64*KN_S + 2*64*VN_S + 64*QP_S)*4)

__global__ __launch_bounds__(128) void flash_tf32_kernel()
{
    extern __shared__ float sm[];
    float* Kn = sm;
    float* Vn = sm + 2*64*KN_S;
    float* QP = sm + 2*64*KN_S + 2*64*VN_S;

    int tid  = threadIdx.x;
    int lane = tid & 31, w = tid >> 5;
    int q = lane & 3, r = lane >> 2;
    int bh = blockIdx.x;
    int qt = 31 - (int)blockIdx.y;      // heavy tiles first
    int q0 = qt << 6;

    const float* Kbase = g_k + (size_t)bh*T_*HDIM;
    const float* Vbase = g_v + (size_t)bh*T_*HDIM;

    // ---- prefetch k-tile 0
    #pragma unroll
    for (int e = 0; e < 8; e++) {
        int idx = e*128 + tid;
        int rr = idx >> 4, c4 = (idx & 15) << 2;
        cp16(&Kn[rr*KN_S + c4], &Kbase[rr*HDIM + c4]);
        cp16(&Vn[rr*VN_S + c4], &Vbase[rr*HDIM + c4]);
    }
    cp_commit();

    // ---- stage Q tile (tf32 bits already)
    const float* Qg = g_q + ((size_t)bh*T_ + q0)*HDIM;
    #pragma unroll
    for (int it = 0; it < 8; it++) {
        int idx = it*128 + tid;
        int rr = idx >> 4, cc = (idx & 15) << 2;
        *(float4*)&QP[rr*QP_S + cc] = *(const float4*)&Qg[rr*HDIM + cc];
    }
    __syncthreads();

    // ---- Q fragments in registers
    unsigned qa[8][4];
    {
        int rb = w*16 + r;
        #pragma unroll
        for (int kk = 0; kk < 8; kk++) {
            qa[kk][0] = __float_as_uint(QP[(rb    )*QP_S + kk*8 + q    ]);
            qa[kk][1] = __float_as_uint(QP[(rb + 8)*QP_S + kk*8 + q    ]);
            qa[kk][2] = __float_as_uint(QP[(rb    )*QP_S + kk*8 + q + 4]);
            qa[kk][3] = __float_as_uint(QP[(rb + 8)*QP_S + kk*8 + q + 4]);
        }
    }

    float o[8][4];
    float m_[2] = {-1e30f, -1e30f};
    float l_[2] = {0.f, 0.f};
    #pragma unroll
    for (int ni = 0; ni < 8; ni++)
        #pragma unroll
        for (int e = 0; e < 4; e++) o[ni][e] = 0.f;

    for (int kt = 0; kt <= qt; kt++) {
        __syncthreads();     // all warps done with the buffer we're about to overwrite
        if (kt < qt) {
            int k1 = (kt + 1) << 6;
            int nb = (kt + 1) & 1;
            const float* Kg1 = Kbase + (size_t)k1*HDIM;
            const float* Vg1 = Vbase + (size_t)k1*HDIM;
            #pragma unroll
            for (int e = 0; e < 8; e++) {
                int idx = e*128 + tid;
                int rr = idx >> 4, c4 = (idx & 15) << 2;
                cp16(&Kn[(nb*64 + rr)*KN_S + c4], &Kg1[rr*HDIM + c4]);
                cp16(&Vn[(nb*64 + rr)*VN_S + c4], &Vg1[rr*HDIM + c4]);
            }
            cp_commit();
            asm volatile("cp.async.wait_group 1;");
        } else {
            asm volatile("cp.async.wait_group 0;");
        }
        __syncthreads();

        int buf = kt & 1;
        const float* Kb = &Kn[buf*64*KN_S];
        const float* Vb = &Vn[buf*64*VN_S];

        // ---- S = Q @ K^T
        float s[8][4];
        #pragma unroll
        for (int ni = 0; ni < 8; ni++)
            #pragma unroll
            for (int e = 0; e < 4; e++) s[ni][e] = 0.f;

        #pragma unroll
        for (int kk = 0; kk < 8; kk++) {
            #pragma unroll
            for (int ni = 0; ni < 8; ni++) {
                unsigned bb[2];
                bb[0] = __float_as_uint(Kb[(ni*8 + r)*KN_S + kk*8 + q    ]);
                bb[1] = __float_as_uint(Kb[(ni*8 + r)*KN_S + kk*8 + q + 4]);
                mma_tf32(s[ni], qa[kk], bb);
            }
        }

        // ---- causal mask (diagonal tile only)
        if (kt == qt) {
            int rowA = q0 + w*16 + r;
            int rowB = rowA + 8;
            int k0 = kt << 6;
            #pragma unroll
            for (int ni = 0; ni < 8; ni++) {
                int colb = k0 + ni*8 + 2*q;
                if (colb     > rowA) s[ni][0] = -1e30f;
                if (colb + 1 > rowA) s[ni][1] = -1e30f;
                if (colb     > rowB) s[ni][2] = -1e30f;
                if (colb + 1 > rowB) s[ni][3] = -1e30f;
            }
        }

        // ---- online softmax
        float mxA = -1e30f, mxB = -1e30f;
        #pragma unroll
        for (int ni = 0; ni < 8; ni++) {
            mxA = fmaxf(mxA, fmaxf(s[ni][0], s[ni][1]));
            mxB = fmaxf(mxB, fmaxf(s[ni][2], s[ni][3]));
        }
        mxA = fmaxf(mxA, __shfl_xor_sync(0xffffffffu, mxA, 1));
        mxA = fmaxf(mxA, __shfl_xor_sync(0xffffffffu, mxA, 2));
        mxB = fmaxf(mxB, __shfl_xor_sync(0xffffffffu, mxB, 1));
        mxB = fmaxf(mxB, __shfl_xor_sync(0xffffffffu, mxB, 2));
        float mnA = fmaxf(m_[0], mxA), mnB = fmaxf(m_[1], mxB);
        float alA = __expf(m_[0] - mnA), alB = __expf(m_[1] - mnB);
        m_[0] = mnA; m_[1] = mnB;
        float sA = 0.f, sB = 0.f;
        #pragma unroll
        for (int ni = 0; ni < 8; ni++) {
            s[ni][0] = __expf(s[ni][0] - mnA);
            s[ni][1] = __expf(s[ni][1] - mnA);
            s[ni][2] = __expf(s[ni][2] - mnB);
            s[ni][3] = __expf(s[ni][3] - mnB);
            sA += s[ni][0] + s[ni][1];
            sB += s[ni][2] + s[ni][3];
        }
        sA += __shfl_xor_sync(0xffffffffu, sA, 1);
        sA += __shfl_xor_sync(0xffffffffu, sA, 2);
        sB += __shfl_xor_sync(0xffffffffu, sB, 1);
        sB += __shfl_xor_sync(0xffffffffu, sB, 2);
        l_[0] = l_[0]*alA + sA;
        l_[1] = l_[1]*alB + sB;
        #pragma unroll
        for (int ni = 0; ni < 8; ni++) {
            o[ni][0] *= alA; o[ni][1] *= alA;
            o[ni][2] *= alB; o[ni][3] *= alB;
        }

        // ---- stage P (tf32 bits) into per-warp rows of QP
        __syncwarp();
        {
            int rb = w*16 + r;
            #pragma unroll
            for (int ni = 0; ni < 8; ni++) {
                *(float2*)&QP[(rb    )*QP_S + ni*8 + 2*q] =
                    make_float2(f2tf_f(s[ni][0]), f2tf_f(s[ni][1]));
                *(float2*)&QP[(rb + 8)*QP_S + ni*8 + 2*q] =
                    make_float2(f2tf_f(s[ni][2]), f2tf_f(s[ni][3]));
            }
        }
        __syncwarp();

        // ---- O += P @ V
        int rb = w*16 + r;
        #pragma unroll
        for (int kk = 0; kk < 8; kk++) {
            unsigned pa[4];
            pa[0] = __float_as_uint(QP[(rb    )*QP_S + kk*8 + q    ]);
            pa[1] = __float_as_uint(QP[(rb + 8)*QP_S + kk*8 + q    ]);
            pa[2] = __float_as_uint(QP[(rb    )*QP_S + kk*8 + q + 4]);
            pa[3] = __float_as_uint(QP[(rb + 8)*QP_S + kk*8 + q + 4]);
            #pragma unroll
            for (int ni = 0; ni < 8; ni++) {
                unsigned vb[2];
                vb[0] = __float_as_uint(Vb[(kk*8 + q    )*VN_S + ni*8 + r]);
                vb[1] = __float_as_uint(Vb[(kk*8 + q + 4)*VN_S + ni*8 + r]);
                mma_tf32(o[ni], pa, vb);
            }
        }
    }

    // ---- epilogue: y (tf32 bits) in [B,T,DM]
    float invA = 1.0f / l_[0], invB = 1.0f / l_[1];
    int b_ = bh >> 3, h = bh & 7;
    int rowA = q0 + w*16 + r;
    int rowB = rowA + 8;
    #pragma unroll
    for (int ni = 0; ni < 8; ni++) {
        int col = h*HDIM + ni*8 + 2*q;
        *(float2*)&g_y[((size_t)b_*T_ + rowA)*DMODEL + col] =
            make_float2(f2tf_f(o[ni][0]*invA), f2tf_f(o[ni][1]*invA));
        *(float2*)&g_y[((size_t)b_*T_ + rowB)*DMODEL + col] =
            make_float2(f2tf_f(o[ni][2]*invB), f2tf_f(o[ni][3]*invB));
    }
}

// ---------------------------------------------------------------------------
extern "C" void kernel_launch(void* const* d_in, const int* in_sizes, int n_in,
                              void* d_out, int out_size)
{
    const float* x     = (const float*)d_in[0];
    const float* w_qkv = (const float*)d_in[1];
    const float* b_qkv = (const float*)d_in[2];
    const float* w_out = (const float*)d_in[3];
    const float* b_out = (const float*)d_in[4];
    float* out = (float*)d_out;

    cudaFuncSetAttribute(flash_tf32_kernel,
                         cudaFuncAttributeMaxDynamicSharedMemorySize, FLASH_SMEM);
    cudaFuncSetAttribute(gemm_tf32_kernel<3*DMODEL, true,  true,  true >,
                         cudaFuncAttributeMaxDynamicSharedMemorySize, GEMM_SMEM);
    cudaFuncSetAttribute(gemm_tf32_kernel<DMODEL, false, false, true >,
                         cudaFuncAttributeMaxDynamicSharedMemorySize, GEMM_SMEM);

    gemm_tf32_kernel<3*DMODEL, true,  true,  true ><<<dim3(12, 128), 256, GEMM_SMEM>>>(x, w_qkv, b_qkv, nullptr);
    rope_kernel<<<16384, 256>>>();
    flash_tf32_kernel<<<dim3(64, 32), 128, FLASH_SMEM>>>();
    gemm_tf32_kernel<DMODEL, false, false, true ><<<dim3(4, 128), 256, GEMM_SMEM>>>(nullptr, w_out, b_out, out);
}

// round 6
// speedup vs baseline: 1.3340x; 1.3340x over previous
#include <cuda_runtime.h>

#define B_      8
#define T_      2048
#define DMODEL  512
#define NHEADS  8
#define HDIM    64
#define BT_     (B_*T_)

// Scratch (device globals) — EXACTLY the R2 footprint (128 MiB): proven safe.
__device__ float g_q[B_*NHEADS*T_*HDIM];   // tf32 bits after rope
__device__ float g_k[B_*NHEADS*T_*HDIM];   // tf32 bits after rope
__device__ float g_v[B_*NHEADS*T_*HDIM];   // tf32 bits (qkv epilogue)
__device__ float g_y[BT_*DMODEL];          // tf32 bits (flash epilogue)

// ---------------------------------------------------------------------------
// helpers
// ---------------------------------------------------------------------------
__device__ __forceinline__ unsigned f2tf(float x) {
    unsigned u;
    asm("cvt.rna.tf32.f32 %0, %1;" : "=r"(u) : "f"(x));
    return u;
}
__device__ __forceinline__ float f2tf_f(float x) { return __uint_as_float(f2tf(x)); }

__device__ __forceinline__ void mma_tf32(float c[4], const unsigned a[4], const unsigned b[2]) {
    asm volatile(
        "mma.sync.aligned.m16n8k8.row.col.f32.tf32.tf32.f32 "
        "{%0,%1,%2,%3},{%4,%5,%6,%7},{%8,%9},{%0,%1,%2,%3};"
        : "+f"(c[0]), "+f"(c[1]), "+f"(c[2]), "+f"(c[3])
        : "r"(a[0]), "r"(a[1]), "r"(a[2]), "r"(a[3]), "r"(b[0]), "r"(b[1]));
}

__device__ __forceinline__ void cp16(void* smem, const void* g) {
    unsigned s = (unsigned)__cvta_generic_to_shared(smem);
    asm volatile("cp.async.cg.shared.global [%0], [%1], 16;" :: "r"(s), "l"(g));
}
__device__ __forceinline__ void cp_commit() { asm volatile("cp.async.commit_group;"); }

// ---------------------------------------------------------------------------
// tf32 GEMM — EXACT R2 structure (best measured: 89us for N=512 variant).
// 128x128x16 tiles, 256 threads (8 warps 2x4), warp tile 64x32.
// cp.async double-buffered; cvt at fragment-load time.
// CVT_A=false when A (g_y) is already tf32-rounded by its producer.
// SCATTER: epilogue scatters qkv (V rounded to tf32); else writes Out fp32.
// ---------------------------------------------------------------------------
template<int N, bool SCATTER, bool CVT_A>
__global__ __launch_bounds__(256) void gemm_tf32_kernel(
    const float* __restrict__ A, const float* __restrict__ W,
    const float* __restrict__ bias, float* __restrict__ Out)
{
    const int K = DMODEL;
    __shared__ float As[2][128][20];
    __shared__ float Bs[2][16][136];
    int tid  = threadIdx.x;
    int lane = tid & 31, warp = tid >> 5;
    int q = lane & 3, r = lane >> 2;
    int wr = warp >> 2, wc = warp & 3;
    int r0 = blockIdx.y << 7, c0 = blockIdx.x << 7;

    const float* Aptr = SCATTER ? A : g_y;

    float acc[4][4][4];
    #pragma unroll
    for (int mi = 0; mi < 4; mi++)
        #pragma unroll
        for (int ni = 0; ni < 4; ni++)
            #pragma unroll
            for (int e = 0; e < 4; e++) acc[mi][ni][e] = 0.f;

    {
        #pragma unroll
        for (int e = 0; e < 2; e++) {
            int idx = e*256 + tid;
            int row = idx >> 2, kq = idx & 3;
            cp16(&As[0][row][kq*4], &Aptr[(size_t)(r0+row)*K + kq*4]);
        }
        #pragma unroll
        for (int e = 0; e < 2; e++) {
            int idx = e*256 + tid;
            int kr = idx >> 5, nq = idx & 31;
            cp16(&Bs[0][kr][nq*4], &W[(size_t)kr*N + c0 + nq*4]);
        }
        cp_commit();
    }

    int buf = 0;
    for (int it = 0; it < 32; it++) {
        asm volatile("cp.async.wait_group 0;");
        __syncthreads();
        if (it + 1 < 32) {
            int k0 = (it+1) << 4;
            int nb = buf ^ 1;
            #pragma unroll
            for (int e = 0; e < 2; e++) {
                int idx = e*256 + tid;
                int row = idx >> 2, kq = idx & 3;
                cp16(&As[nb][row][kq*4], &Aptr[(size_t)(r0+row)*K + k0 + kq*4]);
            }
            #pragma unroll
            for (int e = 0; e < 2; e++) {
                int idx = e*256 + tid;
                int kr = idx >> 5, nq = idx & 31;
                cp16(&Bs[nb][kr][nq*4], &W[(size_t)(k0+kr)*N + c0 + nq*4]);
            }
            cp_commit();
        }
        #pragma unroll
        for (int ks = 0; ks < 2; ks++) {
            unsigned a[4][4], b[4][2];
            #pragma unroll
            for (int mi = 0; mi < 4; mi++) {
                int mb = wr*64 + mi*16;
                if (CVT_A) {
                    a[mi][0] = f2tf(As[buf][mb + r    ][ks*8 + q    ]);
                    a[mi][1] = f2tf(As[buf][mb + r + 8][ks*8 + q    ]);
                    a[mi][2] = f2tf(As[buf][mb + r    ][ks*8 + q + 4]);
                    a[mi][3] = f2tf(As[buf][mb + r + 8][ks*8 + q + 4]);
                } else {
                    a[mi][0] = __float_as_uint(As[buf][mb + r    ][ks*8 + q    ]);
                    a[mi][1] = __float_as_uint(As[buf][mb + r + 8][ks*8 + q    ]);
                    a[mi][2] = __float_as_uint(As[buf][mb + r    ][ks*8 + q + 4]);
                    a[mi][3] = __float_as_uint(As[buf][mb + r + 8][ks*8 + q + 4]);
                }
            }
            #pragma unroll
            for (int ni = 0; ni < 4; ni++) {
                int nb2 = wc*32 + ni*8;
                b[ni][0] = f2tf(Bs[buf][ks*8 + q    ][nb2 + r]);
                b[ni][1] = f2tf(Bs[buf][ks*8 + q + 4][nb2 + r]);
            }
            #pragma unroll
            for (int mi = 0; mi < 4; mi++)
                #pragma unroll
                for (int ni = 0; ni < 4; ni++)
                    mma_tf32(acc[mi][ni], a[mi], b[ni]);
        }
        buf ^= 1;
    }

    #pragma unroll
    for (int mi = 0; mi < 4; mi++) {
        #pragma unroll
        for (int half = 0; half < 2; half++) {
            int row = r0 + wr*64 + mi*16 + r + half*8;
            #pragma unroll
            for (int ni = 0; ni < 4; ni++) {
                int col = c0 + wc*32 + ni*8 + 2*q;
                float v0 = acc[mi][ni][half*2+0] + bias[col];
                float v1 = acc[mi][ni][half*2+1] + bias[col+1];
                if (SCATTER) {
                    int b_ = row >> 11, t = row & (T_-1);
                    int proj = col >> 9;
                    int dm = col & 511;
                    int h = dm >> 6, d = dm & 63;
                    if (proj == 2) { v0 = f2tf_f(v0); v1 = f2tf_f(v1); }  // V pre-rounded for flash
                    float* dst = (proj == 0) ? g_q : (proj == 1) ? g_k : g_v;
                    *(float2*)&dst[(((size_t)(b_<<3) + h)*T_ + t)*HDIM + d] = make_float2(v0, v1);
                } else {
                    *(float2*)&Out[(size_t)row*N + col] = make_float2(v0, v1);
                }
            }
        }
    }
}

// ---------------------------------------------------------------------------
// RoPE on q (scaled by 1/sqrt(D)) and k, in place; writes tf32 bits
// ---------------------------------------------------------------------------
__global__ void rope_kernel()
{
    int idx = blockIdx.x*blockDim.x + threadIdx.x;   // B*H*T*32
    int i  = idx & 31;
    int t  = (idx >> 5) & (T_-1);
    int bh = idx >> 16;
    float invf = exp2f(-(float)i * 0.4152410118609203f);
    float ang  = (float)t * invf;
    float sn, cs;
    sincosf(ang, &sn, &cs);
    int base = (bh*T_ + t)*HDIM + i;
    float q1 = g_q[base], q2 = g_q[base+32];
    g_q[base]    = f2tf_f((q1*cs - q2*sn) * 0.125f);
    g_q[base+32] = f2tf_f((q2*cs + q1*sn) * 0.125f);
    float k1 = g_k[base], k2 = g_k[base+32];
    g_k[base]    = f2tf_f(k1*cs - k2*sn);
    g_k[base+32] = f2tf_f(k2*cs + k1*sn);
}

// ---------------------------------------------------------------------------
// Causal flash attention, tf32 mma (R4 version — passing). 64x64 tiles.
// 4 warps; warp w owns q-rows [w*16, w*16+16).
// K/V pre-rounded tf32 bits in gmem -> cp.async double-buffered natural tiles.
// ---------------------------------------------------------------------------
#define KN_S 68
#define VN_S 72
#define QP_S 76
#define FLASH_SMEM ((2*64*KN_S + 2*64*VN_S + 64*QP_S)*4)

__global__ __launch_bounds__(128) void flash_tf32_kernel()
{
    extern __shared__ float sm[];
    float* Kn = sm;
    float* Vn = sm + 2*64*KN_S;
    float* QP = sm + 2*64*KN_S + 2*64*VN_S;

    int tid  = threadIdx.x;
    int lane = tid & 31, w = tid >> 5;
    int q = lane & 3, r = lane >> 2;
    int bh = blockIdx.x;
    int qt = 31 - (int)blockIdx.y;      // heavy tiles first
    int q0 = qt << 6;

    const float* Kbase = g_k + (size_t)bh*T_*HDIM;
    const float* Vbase = g_v + (size_t)bh*T_*HDIM;

    // ---- prefetch k-tile 0
    #pragma unroll
    for (int e = 0; e < 8; e++) {
        int idx = e*128 + tid;
        int rr = idx >> 4, c4 = (idx & 15) << 2;
        cp16(&Kn[rr*KN_S + c4], &Kbase[rr*HDIM + c4]);
        cp16(&Vn[rr*VN_S + c4], &Vbase[rr*HDIM + c4]);
    }
    cp_commit();

    // ---- stage Q tile (tf32 bits already)
    const float* Qg = g_q + ((size_t)bh*T_ + q0)*HDIM;
    #pragma unroll
    for (int it = 0; it < 8; it++) {
        int idx = it*128 + tid;
        int rr = idx >> 4, cc = (idx & 15) << 2;
        *(float4*)&QP[rr*QP_S + cc] = *(const float4*)&Qg[rr*HDIM + cc];
    }
    __syncthreads();

    // ---- Q fragments in registers
    unsigned qa[8][4];
    {
        int rb = w*16 + r;
        #pragma unroll
        for (int kk = 0; kk < 8; kk++) {
            qa[kk][0] = __float_as_uint(QP[(rb    )*QP_S + kk*8 + q    ]);
            qa[kk][1] = __float_as_uint(QP[(rb + 8)*QP_S + kk*8 + q    ]);
            qa[kk][2] = __float_as_uint(QP[(rb    )*QP_S + kk*8 + q + 4]);
            qa[kk][3] = __float_as_uint(QP[(rb + 8)*QP_S + kk*8 + q + 4]);
        }
    }

    float o[8][4];
    float m_[2] = {-1e30f, -1e30f};
    float l_[2] = {0.f, 0.f};
    #pragma unroll
    for (int ni = 0; ni < 8; ni++)
        #pragma unroll
        for (int e = 0; e < 4; e++) o[ni][e] = 0.f;

    for (int kt = 0; kt <= qt; kt++) {
        __syncthreads();     // all warps done with the buffer we're about to overwrite
        if (kt < qt) {
            int k1 = (kt + 1) << 6;
            int nb = (kt + 1) & 1;
            const float* Kg1 = Kbase + (size_t)k1*HDIM;
            const float* Vg1 = Vbase + (size_t)k1*HDIM;
            #pragma unroll
            for (int e = 0; e < 8; e++) {
                int idx = e*128 + tid;
                int rr = idx >> 4, c4 = (idx & 15) << 2;
                cp16(&Kn[(nb*64 + rr)*KN_S + c4], &Kg1[rr*HDIM + c4]);
                cp16(&Vn[(nb*64 + rr)*VN_S + c4], &Vg1[rr*HDIM + c4]);
            }
            cp_commit();
            asm volatile("cp.async.wait_group 1;");
        } else {
            asm volatile("cp.async.wait_group 0;");
        }
        __syncthreads();

        int buf = kt & 1;
        const float* Kb = &Kn[buf*64*KN_S];
        const float* Vb = &Vn[buf*64*VN_S];

        // ---- S = Q @ K^T
        float s[8][4];
        #pragma unroll
        for (int ni = 0; ni < 8; ni++)
            #pragma unroll
            for (int e = 0; e < 4; e++) s[ni][e] = 0.f;

        #pragma unroll
        for (int kk = 0; kk < 8; kk++) {
            #pragma unroll
            for (int ni = 0; ni < 8; ni++) {
                unsigned bb[2];
                bb[0] = __float_as_uint(Kb[(ni*8 + r)*KN_S + kk*8 + q    ]);
                bb[1] = __float_as_uint(Kb[(ni*8 + r)*KN_S + kk*8 + q + 4]);
                mma_tf32(s[ni], qa[kk], bb);
            }
        }

        // ---- causal mask (diagonal tile only)
        if (kt == qt) {
            int rowA = q0 + w*16 + r;
            int rowB = rowA + 8;
            int k0 = kt << 6;
            #pragma unroll
            for (int ni = 0; ni < 8; ni++) {
                int colb = k0 + ni*8 + 2*q;
                if (colb     > rowA) s[ni][0] = -1e30f;
                if (colb + 1 > rowA) s[ni][1] = -1e30f;
                if (colb     > rowB) s[ni][2] = -1e30f;
                if (colb + 1 > rowB) s[ni][3] = -1e30f;
            }
        }

        // ---- online softmax
        float mxA = -1e30f, mxB = -1e30f;
        #pragma unroll
        for (int ni = 0; ni < 8; ni++) {
            mxA = fmaxf(mxA, fmaxf(s[ni][0], s[ni][1]));
            mxB = fmaxf(mxB, fmaxf(s[ni][2], s[ni][3]));
        }
        mxA = fmaxf(mxA, __shfl_xor_sync(0xffffffffu, mxA, 1));
        mxA = fmaxf(mxA, __shfl_xor_sync(0xffffffffu, mxA, 2));
        mxB = fmaxf(mxB, __shfl_xor_sync(0xffffffffu, mxB, 1));
        mxB = fmaxf(mxB, __shfl_xor_sync(0xffffffffu, mxB, 2));
        float mnA = fmaxf(m_[0], mxA), mnB = fmaxf(m_[1], mxB);
        float alA = __expf(m_[0] - mnA), alB = __expf(m_[1] - mnB);
        m_[0] = mnA; m_[1] = mnB;
        float sA = 0.f, sB = 0.f;
        #pragma unroll
        for (int ni = 0; ni < 8; ni++) {
            s[ni][0] = __expf(s[ni][0] - mnA);
            s[ni][1] = __expf(s[ni][1] - mnA);
            s[ni][2] = __expf(s[ni][2] - mnB);
            s[ni][3] = __expf(s[ni][3] - mnB);
            sA += s[ni][0] + s[ni][1];
            sB += s[ni][2] + s[ni][3];
        }
        sA += __shfl_xor_sync(0xffffffffu, sA, 1);
        sA += __shfl_xor_sync(0xffffffffu, sA, 2);
        sB += __shfl_xor_sync(0xffffffffu, sB, 1);
        sB += __shfl_xor_sync(0xffffffffu, sB, 2);
        l_[0] = l_[0]*alA + sA;
        l_[1] = l_[1]*alB + sB;
        #pragma unroll
        for (int ni = 0; ni < 8; ni++) {
            o[ni][0] *= alA; o[ni][1] *= alA;
            o[ni][2] *= alB; o[ni][3] *= alB;
        }

        // ---- stage P (tf32 bits) into per-warp rows of QP
        __syncwarp();
        {
            int rb = w*16 + r;
            #pragma unroll
            for (int ni = 0; ni < 8; ni++) {
                *(float2*)&QP[(rb    )*QP_S + ni*8 + 2*q] =
                    make_float2(f2tf_f(s[ni][0]), f2tf_f(s[ni][1]));
                *(float2*)&QP[(rb + 8)*QP_S + ni*8 + 2*q] =
                    make_float2(f2tf_f(s[ni][2]), f2tf_f(s[ni][3]));
            }
        }
        __syncwarp();

        // ---- O += P @ V
        int rb = w*16 + r;
        #pragma unroll
        for (int kk = 0; kk < 8; kk++) {
            unsigned pa[4];
            pa[0] = __float_as_uint(QP[(rb    )*QP_S + kk*8 + q    ]);
            pa[1] = __float_as_uint(QP[(rb + 8)*QP_S + kk*8 + q    ]);
            pa[2] = __float_as_uint(QP[(rb    )*QP_S + kk*8 + q + 4]);
            pa[3] = __float_as_uint(QP[(rb + 8)*QP_S + kk*8 + q + 4]);
            #pragma unroll
            for (int ni = 0; ni < 8; ni++) {
                unsigned vb[2];
                vb[0] = __float_as_uint(Vb[(kk*8 + q    )*VN_S + ni*8 + r]);
                vb[1] = __float_as_uint(Vb[(kk*8 + q + 4)*VN_S + ni*8 + r]);
                mma_tf32(o[ni], pa, vb);
            }
        }
    }

    // ---- epilogue: y (tf32 bits) in [B,T,DM]
    float invA = 1.0f / l_[0], invB = 1.0f / l_[1];
    int b_ = bh >> 3, h = bh & 7;
    int rowA = q0 + w*16 + r;
    int rowB = rowA + 8;
    #pragma unroll
    for (int ni = 0; ni < 8; ni++) {
        int col = h*HDIM + ni*8 + 2*q;
        *(float2*)&g_y[((size_t)b_*T_ + rowA)*DMODEL + col] =
            make_float2(f2tf_f(o[ni][0]*invA), f2tf_f(o[ni][1]*invA));
        *(float2*)&g_y[((size_t)b_*T_ + rowB)*DMODEL + col] =
            make_float2(f2tf_f(o[ni][2]*invB), f2tf_f(o[ni][3]*invB));
    }
}

// ---------------------------------------------------------------------------
extern "C" void kernel_launch(void* const* d_in, const int* in_sizes, int n_in,
                              void* d_out, int out_size)
{
    const float* x     = (const float*)d_in[0];
    const float* w_qkv = (const float*)d_in[1];
    const float* b_qkv = (const float*)d_in[2];
    const float* w_out = (const float*)d_in[3];
    const float* b_out = (const float*)d_in[4];
    float* out = (float*)d_out;

    cudaFuncSetAttribute(flash_tf32_kernel,
                         cudaFuncAttributeMaxDynamicSharedMemorySize, FLASH_SMEM);

    gemm_tf32_kernel<3*DMODEL, true,  true ><<<dim3(12, 128), 256>>>(x, w_qkv, b_qkv, nullptr);
    rope_kernel<<<16384, 256>>>();
    flash_tf32_kernel<<<dim3(64, 32), 128, FLASH_SMEM>>>();
    gemm_tf32_kernel<DMODEL, false, false><<<dim3(4, 128), 256>>>(nullptr, w_out, b_out, out);
}